// round 17
// baseline (speedup 1.0000x reference)
#include <cuda_runtime.h>
#include <math.h>
#include <stdint.h>

#define N_TOK 16384
#define DIM   2048
#define NEXP  64
#define KSEL  9
#define EPS_C 0.01f
#define INV_SIG_SQRT2 45.254833995939045f

#define BM 112
#define GRID 147                   // ceil(16384/112)
#define BK 32
#define NCHUNK (DIM / BK)          // 64
#define NSTAGE 4
#define XTS 36                     // x smem row stride (u32)
#define XTILE (BM * XTS)           // 4032 u32
#define WTILE (BK * 128)           // 4096 u32
#define STAGEU (XTILE + WTILE)     // 8128 u32 = 32512 B
#define SMEM_BYTES (NSTAGE * STAGEU * 4)   // 130048 B
#define XV4 (BM * 8)               // 896 float4 per x stage
#define RPW 4                      // epi rows per warp (interleaved)

// logits scratch: [row][128] (0-63 raw dot, 64-127 noise-pre dot) = 8 MB
__device__ __align__(16) float g_lg[(size_t)N_TOK * 128];

__device__ __forceinline__ unsigned long long pack_dup(float a) {
    unsigned long long r;
    unsigned ai = __float_as_uint(a);
    asm("mov.b64 %0, {%1, %1};" : "=l"(r) : "r"(ai));
    return r;
}
__device__ __forceinline__ uint32_t smem_u32(const void* p) {
    uint32_t a;
    asm("{ .reg .u64 t; cvta.to.shared.u64 t, %1; cvt.u32.u64 %0, t; }"
        : "=r"(a) : "l"(p));
    return a;
}
// .cg: bypass L1 (x has no L1 reuse; W reuse is cross-CTA via L2).
__device__ __forceinline__ void cp16(uint32_t dst, const void* src) {
    asm volatile("cp.async.cg.shared.global [%0], [%1], 16;"
                 :: "r"(dst), "l"(src) : "memory");
}

// ---------------- GEMM: fp32 FFMA2, 112x128 per CTA, 147 CTAs (1/SM) ----------------
// (round-15 proven configuration — FROZEN)
extern "C" __global__ void __launch_bounds__(256, 1)
gemm_kernel(const float* __restrict__ x, const float* __restrict__ Wr,
            const float* __restrict__ Wn, float* __restrict__ out)
{
    extern __shared__ uint32_t smu[];
    const uint32_t sbase = smem_u32(smu);
    const int tid = threadIdx.x;
    const int ty  = tid >> 4;        // 0..15 -> rows 7ty..7ty+6
    const int tx  = tid & 15;        // col pairs 2tx+32j
    const int row0 = blockIdx.x * BM;

    // zero the importance/load accumulator region (epi runs strictly after gemm)
    if (blockIdx.x == 0 && tid < 2 * NEXP)
        out[2 * (size_t)N_TOK * NEXP + tid] = 0.f;

    // ---- x cp.async map: 896 float4 over 256 threads x 4 iters (guarded) ----
    const float* xsrc[4];
    uint32_t     xoff[4];
    bool         xact[4];
    #pragma unroll
    for (int i = 0; i < 4; i++) {
        int idx = tid + 256 * i;
        xact[i] = (idx < XV4);
        int r = idx >> 3, seg = idx & 7;
        if (!xact[i]) { r = 0; seg = 0; }
        int grow = row0 + r; if (grow > N_TOK - 1) grow = N_TOK - 1;  // tail clamp
        xsrc[i] = x + (size_t)grow * DIM + seg * 4;
        xoff[i] = (uint32_t)((r * XTS + seg * 4) * 4);
    }
    // ---- W cp.async map ----
    const int wk = tid >> 5, wq = tid & 31;
    const int wcol = wq * 4;
    const float* wsrcbase = (wcol < 64) ? (Wr + wcol) : (Wn + wcol - 64);

    unsigned long long acc[7][4];
    #pragma unroll
    for (int i = 0; i < 7; i++)
        #pragma unroll
        for (int j = 0; j < 4; j++) acc[i][j] = 0ULL;

    auto issue = [&](int c) {
        uint32_t buf = sbase + (uint32_t)((c & (NSTAGE - 1)) * STAGEU * 4);
        #pragma unroll
        for (int i = 0; i < 4; i++)
            if (xact[i]) cp16(buf + xoff[i], xsrc[i] + c * BK);
        #pragma unroll
        for (int i = 0; i < 4; i++) {
            int kk = wk + 8 * i;
            cp16(buf + (uint32_t)((XTILE + kk * 128 + wcol) * 4),
                 wsrcbase + (size_t)(c * BK + kk) * NEXP);
        }
    };

    // prologue: stages 0..2
    #pragma unroll
    for (int p = 0; p < NSTAGE - 1; p++) {
        issue(p);
        asm volatile("cp.async.commit_group;" ::: "memory");
    }

    #pragma unroll 1
    for (int c = 0; c < NCHUNK; c++) {
        if (c < NCHUNK - 2)
            asm volatile("cp.async.wait_group 2;" ::: "memory");
        else if (c == NCHUNK - 2)
            asm volatile("cp.async.wait_group 1;" ::: "memory");
        else
            asm volatile("cp.async.wait_group 0;" ::: "memory");
        __syncthreads();
        if (c + NSTAGE - 1 < NCHUNK) {
            issue(c + NSTAGE - 1);              // stage (c-1)&3: readers passed barrier
            asm volatile("cp.async.commit_group;" ::: "memory");
        }

        const uint32_t* buf = smu + (c & (NSTAGE - 1)) * STAGEU;
        const float* xs = (const float*)buf;
        const float* ws = (const float*)(buf + XTILE);
        #pragma unroll 4
        for (int kk = 0; kk < BK; kk++) {
            unsigned long long b2[4];
            #pragma unroll
            for (int j = 0; j < 4; j++)
                b2[j] = *(const unsigned long long*)(ws + kk * 128 + 2 * tx + 32 * j);
            unsigned long long a2[7];
            #pragma unroll
            for (int i = 0; i < 7; i++)
                a2[i] = pack_dup(xs[(7 * ty + i) * XTS + kk]);
            #pragma unroll
            for (int i = 0; i < 7; i++)
                #pragma unroll
                for (int j = 0; j < 4; j++)
                    asm("fma.rn.f32x2 %0, %1, %2, %0;"
                        : "+l"(acc[i][j]) : "l"(a2[i]), "l"(b2[j]));
        }
    }

    // ---- write logits (STG.64, coalesced); guard tail CTA ----
    #pragma unroll
    for (int i = 0; i < 7; i++) {
        int row = row0 + 7 * ty + i;
        if (row < N_TOK) {
            #pragma unroll
            for (int j = 0; j < 4; j++)
                *(unsigned long long*)(g_lg + (size_t)row * 128 + 2 * tx + 32 * j)
                    = acc[i][j];
        }
    }
}

// ---------------- epilogue: RPW rows per warp, interleaved chains ----------------
__device__ __forceinline__ uint32_t redux_max(uint32_t v) {
    uint32_t r;
    asm("redux.sync.max.u32 %0, %1, 0xffffffff;" : "=r"(r) : "r"(v));
    return r;
}
__device__ __forceinline__ uint32_t ordkey(float f) {
    uint32_t u = __float_as_uint(f);
    return ((int)u < 0) ? ~u : (u | 0x80000000u);
}
__device__ __forceinline__ float ordinv(uint32_t k) {
    return __uint_as_float(((int)k < 0) ? (k ^ 0x80000000u) : ~k);
}

extern "C" __global__ void __launch_bounds__(256)
epi_kernel(const float* __restrict__ br,  const float* __restrict__ bn,
           const float* __restrict__ neps, const float* __restrict__ gum,
           float* __restrict__ out)
{
    __shared__ float imp_s[64], load_s[64];
    const int tid = threadIdx.x;
    const int wid = tid >> 5;
    const int lane = tid & 31;
    if (tid < 64) { imp_s[tid] = 0.f; load_s[tid] = 0.f; }
    __syncthreads();

    const int e0 = lane, e1 = lane + 32;
    const float brv0 = br[e0], brv1 = br[e1];
    const float bnv0 = bn[e0], bnv1 = bn[e1];
    const int row0 = (blockIdx.x * 8 + wid) * RPW;   // grid 512: RPW rows per warp

    float raw0[RPW], raw1[RPW], sd0[RPW], sd1[RPW];
    float nz0[RPW], nz1[RPW], gg0[RPW], gg1[RPW];

    #pragma unroll
    for (int r = 0; r < RPW; r++) {
        const float* L = g_lg + (size_t)(row0 + r) * 128;
        raw0[r] = L[e0] + brv0;
        raw1[r] = L[e1] + brv1;
        float p0 = L[64 + e0] + bnv0, p1 = L[64 + e1] + bnv1;
        // softplus kept full precision: feeds top-k selection
        sd0[r] = fmaxf(p0, 0.f) + log1pf(expf(-fabsf(p0))) + EPS_C;
        sd1[r] = fmaxf(p1, 0.f) + log1pf(expf(-fabsf(p1))) + EPS_C;
        nz0[r] = fmaf(neps[(size_t)(row0 + r) * NEXP + e0], sd0[r], raw0[r]);
        nz1[r] = fmaf(neps[(size_t)(row0 + r) * NEXP + e1], sd1[r], raw1[r]);
        gg0[r] = gum[(size_t)(row0 + r) * NEXP + e0];
        gg1[r] = gum[(size_t)(row0 + r) * NEXP + e1];
    }

    // ---- top-9, RPW rows interleaved (exact, tie -> lowest idx) ----
    uint32_t k0[RPW], k1[RPW];
    float h0[RPW], h1[RPW], thr[RPW], m1[RPW];
    #pragma unroll
    for (int r = 0; r < RPW; r++) {
        k0[r] = ordkey(nz0[r]); k1[r] = ordkey(nz1[r]);
        h0[r] = 0.f; h1[r] = 0.f;
    }
    #pragma unroll 1
    for (int t = 0; t < KSEL; t++) {
        uint32_t M[RPW];
        #pragma unroll
        for (int r = 0; r < RPW; r++)
            M[r] = redux_max(k0[r] > k1[r] ? k0[r] : k1[r]);
        #pragma unroll
        for (int r = 0; r < RPW; r++) {
            if (t == 0) m1[r] = ordinv(M[r]);
            thr[r] = ordinv(M[r]);
        }
        unsigned b0[RPW];
        #pragma unroll
        for (int r = 0; r < RPW; r++)
            b0[r] = __ballot_sync(0xffffffffu, k0[r] == M[r]);
        #pragma unroll
        for (int r = 0; r < RPW; r++) {
            if (b0[r]) {                         // warp-uniform branch
                if (lane == __ffs(b0[r]) - 1) { h0[r] = 1.f; k0[r] = 0u; }
            } else {
                unsigned b1 = __ballot_sync(0xffffffffu, k1[r] == M[r]);
                if (lane == __ffs(b1) - 1) { h1[r] = 1.f; k1[r] = 0u; }
            }
        }
    }

    // ---- softmax maxes via redux (interleaved); fast exp/rcp ----
    float m2[RPW], m3[RPW];
    #pragma unroll
    for (int r = 0; r < RPW; r++)
        m2[r] = ordinv(redux_max(ordkey(fmaxf(nz0[r] + gg0[r], nz1[r] + gg1[r]))));
    #pragma unroll
    for (int r = 0; r < RPW; r++)
        m3[r] = ordinv(redux_max(ordkey(fmaxf(raw0[r], raw1[r]))));

    float E10[RPW], E11[RPW], E20[RPW], E21[RPW], E30[RPW], E31[RPW];
    float s1[RPW], s2[RPW], s3[RPW];
    #pragma unroll
    for (int r = 0; r < RPW; r++) {
        E10[r] = __expf(nz0[r] - m1[r]);
        E11[r] = __expf(nz1[r] - m1[r]);
        E20[r] = __expf(nz0[r] + gg0[r] - m2[r]);
        E21[r] = __expf(nz1[r] + gg1[r] - m2[r]);
        E30[r] = __expf(raw0[r] - m3[r]);
        E31[r] = __expf(raw1[r] - m3[r]);
        s1[r] = E10[r] + E11[r];
        s2[r] = E20[r] + E21[r];
        s3[r] = E30[r] + E31[r];
    }
    #pragma unroll
    for (int o = 16; o; o >>= 1)
        #pragma unroll
        for (int r = 0; r < RPW; r++) {
            s1[r] += __shfl_xor_sync(0xffffffffu, s1[r], o);
            s2[r] += __shfl_xor_sync(0xffffffffu, s2[r], o);
            s3[r] += __shfl_xor_sync(0xffffffffu, s3[r], o);
        }

    float imp0 = 0.f, imp1 = 0.f, ld0 = 0.f, ld1 = 0.f;
    #pragma unroll
    for (int r = 0; r < RPW; r++) {
        float i1 = __fdividef(1.f, s1[r]);
        float i2 = __fdividef(1.f, s2[r]);   // cancels in expert_mask
        float i3 = __fdividef(1.f, s3[r]);
        float ms0 = E20[r] * i2, ms1 = E21[r] * i2;
        float* om  = out + (size_t)(row0 + r) * NEXP;
        float* orp = out + (size_t)N_TOK * NEXP + (size_t)(row0 + r) * NEXP;
        om[e0]  = (h0[r] - ms0) + ms0;
        om[e1]  = (h1[r] - ms1) + ms1;
        orp[e0] = E10[r] * i1;
        orp[e1] = E11[r] * i1;
        imp0 += E30[r] * i3;
        imp1 += E31[r] * i3;
        // erf kept exact: 45x slope on the load output
        float z0 = (thr[r] - raw0[r]) / sd0[r];
        float z1 = (thr[r] - raw1[r]) / sd1[r];
        ld0 += 0.5f * (1.f - erff(z0 * INV_SIG_SQRT2));
        ld1 += 0.5f * (1.f - erff(z1 * INV_SIG_SQRT2));
    }

    atomicAdd(&imp_s[e0], imp0);
    atomicAdd(&imp_s[e1], imp1);
    atomicAdd(&load_s[e0], ld0);
    atomicAdd(&load_s[e1], ld1);
    __syncthreads();
    if (tid < 64) {
        atomicAdd(out + 2 * (size_t)N_TOK * NEXP + tid,        imp_s[tid]);
        atomicAdd(out + 2 * (size_t)N_TOK * NEXP + NEXP + tid, load_s[tid]);
    }
}

extern "C" void kernel_launch(void* const* d_in, const int* in_sizes, int n_in,
                              void* d_out, int out_size)
{
    const float* x    = (const float*)d_in[0];
    const float* Wr   = (const float*)d_in[1];
    const float* br   = (const float*)d_in[2];
    const float* Wn   = (const float*)d_in[3];
    const float* bn   = (const float*)d_in[4];
    const float* neps = (const float*)d_in[5];
    const float* gum  = (const float*)d_in[6];
    float* out = (float*)d_out;

    cudaFuncSetAttribute(gemm_kernel,
                         cudaFuncAttributeMaxDynamicSharedMemorySize, SMEM_BYTES);
    gemm_kernel<<<GRID, 256, SMEM_BYTES>>>(x, Wr, Wn, out);

    epi_kernel<<<N_TOK / (8 * RPW), 256>>>(br, bn, neps, gum, out);
}